// round 15
// baseline (speedup 1.0000x reference)
#include <cuda_runtime.h>
#include <math.h>

#define BB 2
#define NN 4096
#define KK 30

#define SZ_POS (BB*NN*KK*16)
#define SZ_AD  (BB*NN*3)
#define SZ_OF  (BB*NN*KK*3)
#define SZ_GS  (BB*NN*KK*15)
#define SZ_DN  (BB*NN*KK)

#define OFF_POS 0
#define OFF_AD  (OFF_POS + SZ_POS)
#define OFF_OF  (OFF_AD  + SZ_AD)
#define OFF_GS  (OFF_OF  + SZ_OF)
#define OFF_DN  (OFF_GS  + SZ_GS)
#define OFF_EI  (OFF_DN  + SZ_DN)

typedef unsigned long long u64;
typedef unsigned int       u32;

// ---- scratch ----
static __device__ float4 g_pts4[BB*NN];   // (x, y, z, |p|^2)

// ---- packed f32x2 helpers ----
__device__ __forceinline__ u64 pack2(float lo, float hi){
    u64 d; asm("mov.b64 %0, {%1, %2};" : "=l"(d) : "f"(lo), "f"(hi)); return d;
}
__device__ __forceinline__ u64 fma2(u64 a, u64 b, u64 c){
    u64 d; asm("fma.rn.f32x2 %0, %1, %2, %3;" : "=l"(d) : "l"(a), "l"(b), "l"(c)); return d;
}
__device__ __forceinline__ u64 mul2(u64 a, u64 b){
    u64 d; asm("mul.rn.f32x2 %0, %1, %2;" : "=l"(d) : "l"(a), "l"(b)); return d;
}
__device__ __forceinline__ u64 add2(u64 a, u64 b){
    u64 d; asm("add.rn.f32x2 %0, %1, %2;" : "=l"(d) : "l"(a), "l"(b)); return d;
}

// ---- exact-rounding helpers (OUTPUT values / selection keys) ----
__device__ __forceinline__ float fadd_(float a, float b){ return __fadd_rn(a,b); }
__device__ __forceinline__ float fsub_(float a, float b){ return __fsub_rn(a,b); }
__device__ __forceinline__ float fmul_(float a, float b){ return __fmul_rn(a,b); }
__device__ __forceinline__ float dot3_(float ax,float ay,float az,
                                       float bx,float by,float bz){
    return fadd_(fadd_(fmul_(ax,bx), fmul_(ay,by)), fmul_(az,bz));
}
__device__ __forceinline__ void norm3_(float &x, float &y, float &z){
    float n = __fsqrt_rn(dot3_(x,y,z,x,y,z));
    n = fmaxf(n, 1e-12f);
    x = __fdiv_rn(x,n); y = __fdiv_rn(y,n); z = __fdiv_rn(z,n);
}
__device__ __forceinline__ void cross3_(float ax,float ay,float az,
                                        float bx,float by,float bz,
                                        float &cx,float &cy,float &cz){
    cx = fsub_(fmul_(ay,bz), fmul_(az,by));
    cy = fsub_(fmul_(az,bx), fmul_(ax,bz));
    cz = fsub_(fmul_(ax,by), fmul_(ay,bx));
}
__device__ __forceinline__ float d2_exact(float xi,float yi,float zi,
                                          float xj,float yj,float zj){
    float dx = fsub_(xj,xi), dy = fsub_(yj,yi), dz = fsub_(zj,zi);
    return fadd_(fadd_(fmul_(dx,dx), fmul_(dy,dy)), fmul_(dz,dz));
}

// ---- FP32 Cody-Waite 2pi reduction ----
#define INV_2PI  0.15915494309189535f
#define PI2_C1   6.2831855f
#define PI2_C2  -1.7484555e-07f
#define PI2_C3  -5.4469782e-15f
__device__ __forceinline__ float red2pi_(float ang){
    float k = rintf(ang * INV_2PI);
    float r = fmaf(-k, PI2_C1, ang);
    r = fmaf(-k, PI2_C2, r);
    r = fmaf(-k, PI2_C3, r);
    return r;
}

// ---- per-node orientation matrix + AD ----
__device__ void node_work(const float* __restrict__ X, float* __restrict__ outAD,
                          int id, float* __restrict__ sOmRow){
    int b = id / NN, n = id % NN;

    float O0=0,O1=0,O2=0,O3v=0,O4=0,O5=0,O6=0,O7=0,O8=0;
    float a0=0,a1=0,a2=0;

    if (n >= 1 && n <= NN-3){
        const float* Xb = X + b*NN*3;
        float p0x=Xb[(n-1)*3+0], p0y=Xb[(n-1)*3+1], p0z=Xb[(n-1)*3+2];
        float p1x=Xb[(n  )*3+0], p1y=Xb[(n  )*3+1], p1z=Xb[(n  )*3+2];
        float p2x=Xb[(n+1)*3+0], p2y=Xb[(n+1)*3+1], p2z=Xb[(n+1)*3+2];
        float p3x=Xb[(n+2)*3+0], p3y=Xb[(n+2)*3+1], p3z=Xb[(n+2)*3+2];

        float u2x=fsub_(p1x,p0x), u2y=fsub_(p1y,p0y), u2z=fsub_(p1z,p0z); norm3_(u2x,u2y,u2z);
        float u1x=fsub_(p2x,p1x), u1y=fsub_(p2y,p1y), u1z=fsub_(p2z,p1z); norm3_(u1x,u1y,u1z);
        float u0x=fsub_(p3x,p2x), u0y=fsub_(p3y,p2y), u0z=fsub_(p3z,p2z); norm3_(u0x,u0y,u0z);

        float n2x,n2y,n2z; cross3_(u2x,u2y,u2z,u1x,u1y,u1z,n2x,n2y,n2z); norm3_(n2x,n2y,n2z);
        float n1x,n1y,n1z; cross3_(u1x,u1y,u1z,u0x,u0y,u0z,n1x,n1y,n1z); norm3_(n1x,n1y,n1z);

        const float lo = (float)(-1.0 + 1e-6);
        const float hi = (float)( 1.0 - 1e-6);
        float cosA = fminf(fmaxf(-dot3_(u1x,u1y,u1z,u0x,u0y,u0z), lo), hi);
        float A = acosf(cosA);
        float cosD = fminf(fmaxf(dot3_(n2x,n2y,n2z,n1x,n1y,n1z), lo), hi);
        float s = dot3_(u2x,u2y,u2z,n1x,n1y,n1z);
        float sg = (s > 0.0f) ? 1.0f : ((s < 0.0f) ? -1.0f : 0.0f);
        float Dang = fmul_(sg, acosf(cosD));

        float sA = sinf(A);
        a0 = cosf(A);
        a1 = fmul_(sA, cosf(Dang));
        a2 = fmul_(sA, sinf(Dang));

        float o1x=fsub_(u2x,u1x), o1y=fsub_(u2y,u1y), o1z=fsub_(u2z,u1z); norm3_(o1x,o1y,o1z);
        float cx,cy,cz; cross3_(o1x,o1y,o1z,n2x,n2y,n2z,cx,cy,cz);
        O0=o1x; O1=o1y; O2=o1z; O3v=n2x; O4=n2y; O5=n2z; O6=cx; O7=cy; O8=cz;
    }
    sOmRow[0]=O0; sOmRow[1]=O1; sOmRow[2]=O2; sOmRow[3]=O3v; sOmRow[4]=O4;
    sOmRow[5]=O5; sOmRow[6]=O6; sOmRow[7]=O7; sOmRow[8]=O8;
    outAD[id*3+0]=a0; outAD[id*3+1]=a1; outAD[id*3+2]=a2;
}

// ---- pre-pass: pack coords + squared norms ----
__global__ void pack_kernel(const float* __restrict__ X){
    int id = blockIdx.x*blockDim.x + threadIdx.x;
    if (id < BB*NN){
        float x = X[id*3+0], y = X[id*3+1], z = X[id*3+2];
        g_pts4[id] = make_float4(x, y, z, fmaf(z,z, fmaf(y,y, x*x)));
    }
}

// ============================================================================
// Fused kernel v15: sampled threshold + single verified packed scan.
// Exactness: scan keeps {fast-d2' < 1.25*thr}; runtime certificate
// strict = #{fast-d2' < thr} >= 30 guarantees the kept set contains the
// exact top-30 (margin 0.25*thr >> fp error). Fallback rescan otherwise.
// ============================================================================
#define TPB 256
#define RB  8
#define CAP 288
#define SMP 512

__global__ __launch_bounds__(TPB) void fused_kernel(
    const float* __restrict__ X, float* __restrict__ out)
{
    __shared__ u64   cand[RB][CAP];    // 18KB
    __shared__ u64   sp  [RB][CAP];    // 18KB (rank scratch)
    __shared__ float stD[RB][KK];
    __shared__ int   stI[RB][KK];
    __shared__ float sOm[RB][9];
    __shared__ float sThrB[RB];
    __shared__ float sfreq[8];
    __shared__ float smu[15];
    __shared__ int   scnt[RB];
    __shared__ int   sstr[RB];

    float* outP  = out + OFF_POS;
    float* outAD = out + OFF_AD;
    float* outO  = out + OFF_OF;
    float* outG  = out + OFF_GS;
    float* outD  = out + OFF_DN;
    float* outE  = out + OFF_EI;

    const int t = threadIdx.x, w = t >> 5, lane = t & 31;
    const int blk = blockIdx.x;
    const int b   = blk / (NN/RB);
    const int r0  = (blk % (NN/RB))*RB;
    const int bNN = b*NN;
    const float* Xb = X + b*NN*3;
    const u32 FULL = 0xffffffffu;

    if (t < RB){
        node_work(X, outAD, bNN + r0 + t, sOm[t]);
        scnt[t] = 0;
        sstr[t] = 0;
    }
    if (t >= 32 && t < 64){
        int u = t - 32;
        if (u < 8){
            float argf = __fmul_rn((float)(2*u), -0.5756462732485115f);
            sfreq[u] = (float)exp((double)argf);
        }
        if (u < 15) smu[u] = (float)((double)u * (20.0/14.0));
    }

    // packed row registers: pair (q, q+4); nr biased by +1.01
    u64 xr2[4], yr2[4], zr2[4], nr2[4];
    #pragma unroll
    for (int q = 0; q < 4; q++){
        float4 pa = g_pts4[bNN + r0 + q];
        float4 pb = g_pts4[bNN + r0 + q + 4];
        xr2[q] = pack2(pa.x, pb.x);
        yr2[q] = pack2(pa.y, pb.y);
        zr2[q] = pack2(pa.z, pb.z);
        nr2[q] = pack2(pa.w + 1.01f, pb.w + 1.01f);
    }
    const u64 M2 = pack2(-2.0f, -2.0f);

    // own-row scalars for sample/fallback (warp w = row w)
    float4 prow = g_pts4[bNN + r0 + w];
    const float xi_s = prow.x, yi_s = prow.y, zi_s = prow.z;
    const float nrb_s = prow.w + 1.01f;

    // ---- sample phase: 512 points -> octave hist -> thr_base ----
    {
        u64 h0 = 0ull, h1 = 0ull;
        #pragma unroll 4
        for (int q = 0; q < SMP/32; q++){
            int j = q*32 + lane;
            float4 p = g_pts4[bNN + j];
            float s  = fmaf(zi_s, p.z, fmaf(yi_s, p.y, xi_s*p.x));
            float d2 = fmaf(-2.0f, s, nrb_s + p.w);
            int bin = (int)((__float_as_uint(d2) - 0x3F800000u) >> 23);
            bin = max(0, min(15, bin));
            u64 one = 1ull << ((bin & 7) << 3);
            if (bin < 8) h0 += one; else h1 += one;
        }
        const u64 M8 = 0x00FF00FF00FF00FFull;
        u64 a0 =  h0       & M8;
        u64 a1 = (h0 >> 8) & M8;
        u64 a2 =  h1       & M8;
        u64 a3 = (h1 >> 8) & M8;
        #pragma unroll
        for (int off = 16; off; off >>= 1){
            a0 += __shfl_xor_sync(FULL, a0, off);
            a1 += __shfl_xor_sync(FULL, a1, off);
            a2 += __shfl_xor_sync(FULL, a2, off);
            a3 += __shfl_xor_sync(FULL, a3, off);
        }
        int cum = 0, T = 15;
        #pragma unroll
        for (int bb = 0; bb < 16; bb++){
            u64 src = (bb < 8) ? ((bb & 1) ? a1 : a0) : ((bb & 1) ? a3 : a2);
            cum += (int)((src >> (((bb >> 1) & 3) << 4)) & 0xFFFFull);
            if (cum >= 8){ T = bb; break; }
        }
        if (lane == 0)
            sThrB[w] = __uint_as_float((u32)(128 + min(T,14)) << 23); // 2^(T+1)
    }
    __syncthreads();

    // packed thresholds: keep = 1.25*thr_base, strict = thr_base (negated)
    u64 nThrK2[4], nThrB2[4];
    #pragma unroll
    for (int q = 0; q < 4; q++){
        nThrK2[q] = pack2(-1.25f*sThrB[q], -1.25f*sThrB[q+4]);
        nThrB2[q] = pack2(-sThrB[q],       -sThrB[q+4]);
    }

    // ---- single packed scan: keep-append + strict count ----
    #pragma unroll 2
    for (int m = 0; m < NN/TPB; m++){
        int j = m*TPB + t;
        float4 p = g_pts4[bNN + j];
        u64 xjj = pack2(p.x, p.x);
        u64 yjj = pack2(p.y, p.y);
        u64 zjj = pack2(p.z, p.z);
        u64 njj = pack2(p.w, p.w);
        #pragma unroll
        for (int q = 0; q < 4; q++){
            u64 s2 = fma2(xr2[q], xjj, fma2(yr2[q], yjj, mul2(zr2[q], zjj)));
            u64 d2 = fma2(M2, s2, add2(nr2[q], njj));
            u64 df = add2(d2, nThrK2[q]);
            if (df & 0x8000000080000000ull){
                u64 dfb = add2(d2, nThrB2[q]);
                if ((u32)(df >> 31) & 1u){
                    int pos = atomicAdd(&scnt[q], 1);
                    if (pos < CAP) cand[q][pos] = (u64)j;
                    if ((u32)(dfb >> 31) & 1u) atomicAdd(&sstr[q], 1);
                }
                if (df >> 63){
                    int pos = atomicAdd(&scnt[q+4], 1);
                    if (pos < CAP) cand[q+4][pos] = (u64)j;
                    if (dfb >> 63) atomicAdd(&sstr[q+4], 1);
                }
            }
        }
    }
    __syncthreads();

    // ---- per-row certificate check + fallback rescan (warp w = row w) ----
    int c;
    {
        int cnt = scnt[w], str = sstr[w];
        int att = 0;
        while ((str < KK || cnt > CAP) && att < 24){
            if (lane == 0){
                float tb = sThrB[w];
                sThrB[w] = (str < KK) ? tb*1.8f : tb*0.66f;
            }
            __syncwarp();
            float tb = sThrB[w];
            float tk = 1.25f*tb;
            cnt = 0; str = 0;
            for (int m = 0; m < NN/32; m++){
                int j = m*32 + lane;
                float4 p = g_pts4[bNN + j];
                float s  = fmaf(zi_s, p.z, fmaf(yi_s, p.y, xi_s*p.x));
                float d2 = fmaf(-2.0f, s, nrb_s + p.w);
                bool kp = d2 < tk;
                u32 mk = __ballot_sync(FULL, kp);
                str += __popc(__ballot_sync(FULL, d2 < tb));
                if (kp){
                    int pos = cnt + __popc(mk & ((1u << lane) - 1u));
                    if (pos < CAP) cand[w][pos] = (u64)j;
                }
                cnt += __popc(mk);
            }
            att++;
        }
        c = min(cnt, CAP);
    }

    // ---- extraction: exact (D, j) keys + split-rank (warp w = row w) ----
    {
        const int row = r0 + w;
        const int base = (bNN + row)*KK;
        const float xi = Xb[row*3+0], yi = Xb[row*3+1], zi = Xb[row*3+2];

        for (int idx = lane; idx < c; idx += 32){
            u32 j = (u32)cand[w][idx];
            float4 pj = g_pts4[bNN + j];
            float d2 = d2_exact(xi,yi,zi, pj.x,pj.y,pj.z);
            float D  = __fsqrt_rn(fadd_(d2, 1e-6f));
            cand[w][idx] = ((u64)__float_as_uint(D) << 32) | j;
        }
        __syncwarp();

        // pivot: thr_base mapped to exact-D domain (any pivot is valid)
        float pd2 = fmaxf(sThrB[w] - 1.01f, 0.0f);
        float pD  = __fsqrt_rn(fadd_(pd2, 1e-6f));
        const u64 Kp = ((u64)__float_as_uint(pD)) << 32;
        u64* spw = sp[w];

        const int iters = (c + 31) >> 5;
        int totA = 0;
        for (int u = 0; u < iters; u++){
            int idx = u*32 + lane;
            bool A = (idx < c) && (cand[w][idx] < Kp);
            totA += __popc(__ballot_sync(FULL, A));
        }
        int runA = 0, runB = 0;
        for (int u = 0; u < iters; u++){
            int idx = u*32 + lane;
            bool valid = idx < c;
            u64 k = valid ? cand[w][idx] : 0xFFFFFFFFFFFFFFFFull;
            bool A = valid && (k < Kp);
            u32 mA = __ballot_sync(FULL, A);
            u32 mB = __ballot_sync(FULL, valid && !A);
            if (valid){
                u32 below = (1u << lane) - 1u;
                int pos = A ? (runA + __popc(mA & below))
                            : (totA + runB + __popc(mB & below));
                spw[pos] = k;
            }
            runA += __popc(mA);
            runB += __popc(mB);
        }
        __syncwarp();

        for (int idx = lane; idx < c; idx += 32){
            u64 k = spw[idx];
            bool isA = idx < totA;
            int s0 = isA ? 0 : totA;
            int s1 = isA ? totA : c;
            int rank = isA ? 0 : totA;
            for (int cc = s0; cc < s1; cc++)
                rank += (spw[cc] < k) ? 1 : 0;
            if (rank < KK){
                u32 jj = (u32)(k & 0xFFFFFFFFull);
                float D = __uint_as_float((u32)(k >> 32));
                outD[base + rank] = D;
                outE[base + rank] = (float)jj;
                stD[w][rank] = D;
                stI[w][rank] = (int)jj;
            }
        }
    }
    __syncthreads();

    // ---- edge phase A: positional encodings (8 x 30 x 16, coalesced) ----
    for (int id = t; id < RB*KK*16; id += TPB){
        int r = id / (KK*16);
        int q = id - r*(KK*16);
        int k = q >> 4, m = q & 15;
        int i = r0 + r;
        int j = stI[r][k];
        float d = fsub_((float)j, (float)i);
        float ang = fmul_(d, sfreq[m & 7]);
        float rr = red2pi_(ang);
        outP[(size_t)(bNN + i)*(KK*16) + q] = (m < 8) ? __cosf(rr) : __sinf(rr);
    }

    // ---- edge phase B: gaussian smearing (8 x 30 x 15, coalesced) ----
    for (int id = t; id < RB*KK*15; id += TPB){
        int r = id / (KK*15);
        int q = id - r*(KK*15);
        int k = q / 15, m = q - k*15;
        float D  = stD[r][k];
        float tt = fsub_(D, smu[m]) * 0.74999998f;
        outG[(size_t)(bNN + r0 + r)*(KK*15) + q] = __expf(-tt*tt);
    }

    // ---- edge phase C: dU via rsqrt normalize (8 x 30 edges) ----
    if (t < RB*KK){
        int r = t / KK, k = t - r*KK;
        int i = r0 + r;
        int j = stI[r][k];
        float dx = fsub_(Xb[j*3+0], Xb[i*3+0]);
        float dy = fsub_(Xb[j*3+1], Xb[i*3+1]);
        float dz = fsub_(Xb[j*3+2], Xb[i*3+2]);
        const float* Om = sOm[r];
        float v0 = dot3_(Om[0],Om[1],Om[2], dx,dy,dz);
        float v1 = dot3_(Om[3],Om[4],Om[5], dx,dy,dz);
        float v2 = dot3_(Om[6],Om[7],Om[8], dx,dy,dz);
        float s  = dot3_(v0,v1,v2,v0,v1,v2);
        float rn = rsqrtf(fmaxf(s, 1e-24f));
        size_t o = (size_t)((bNN + i)*KK + k)*3;
        outO[o+0] = v0*rn;
        outO[o+1] = v1*rn;
        outO[o+2] = v2*rn;
    }
}

// ============================================================================
extern "C" void kernel_launch(void* const* d_in, const int* in_sizes, int n_in,
                              void* d_out, int out_size)
{
    const float* X = (const float*)d_in[0];
    float* out = (float*)d_out;
    pack_kernel<<<(BB*NN + 255)/256, 256>>>(X);
    fused_kernel<<<BB*NN/RB, TPB>>>(X, out);
}

// round 16
// speedup vs baseline: 1.5374x; 1.5374x over previous
#include <cuda_runtime.h>
#include <math.h>

#define BB 2
#define NN 4096
#define KK 30

#define SZ_POS (BB*NN*KK*16)
#define SZ_AD  (BB*NN*3)
#define SZ_OF  (BB*NN*KK*3)
#define SZ_GS  (BB*NN*KK*15)
#define SZ_DN  (BB*NN*KK)

#define OFF_POS 0
#define OFF_AD  (OFF_POS + SZ_POS)
#define OFF_OF  (OFF_AD  + SZ_AD)
#define OFF_GS  (OFF_OF  + SZ_OF)
#define OFF_DN  (OFF_GS  + SZ_GS)
#define OFF_EI  (OFF_DN  + SZ_DN)

typedef unsigned long long u64;
typedef unsigned int       u32;

// ---- scratch ----
static __device__ float4 g_pts4[BB*NN];   // (x, y, z, |p|^2)

// ---- packed f32x2 helpers ----
__device__ __forceinline__ u64 pack2(float lo, float hi){
    u64 d; asm("mov.b64 %0, {%1, %2};" : "=l"(d) : "f"(lo), "f"(hi)); return d;
}
__device__ __forceinline__ u64 fma2(u64 a, u64 b, u64 c){
    u64 d; asm("fma.rn.f32x2 %0, %1, %2, %3;" : "=l"(d) : "l"(a), "l"(b), "l"(c)); return d;
}
__device__ __forceinline__ u64 mul2(u64 a, u64 b){
    u64 d; asm("mul.rn.f32x2 %0, %1, %2;" : "=l"(d) : "l"(a), "l"(b)); return d;
}
__device__ __forceinline__ u64 add2(u64 a, u64 b){
    u64 d; asm("add.rn.f32x2 %0, %1, %2;" : "=l"(d) : "l"(a), "l"(b)); return d;
}

// ---- exact-rounding helpers (OUTPUT values / selection keys) ----
__device__ __forceinline__ float fadd_(float a, float b){ return __fadd_rn(a,b); }
__device__ __forceinline__ float fsub_(float a, float b){ return __fsub_rn(a,b); }
__device__ __forceinline__ float fmul_(float a, float b){ return __fmul_rn(a,b); }
__device__ __forceinline__ float dot3_(float ax,float ay,float az,
                                       float bx,float by,float bz){
    return fadd_(fadd_(fmul_(ax,bx), fmul_(ay,by)), fmul_(az,bz));
}
__device__ __forceinline__ void norm3_(float &x, float &y, float &z){
    float n = __fsqrt_rn(dot3_(x,y,z,x,y,z));
    n = fmaxf(n, 1e-12f);
    x = __fdiv_rn(x,n); y = __fdiv_rn(y,n); z = __fdiv_rn(z,n);
}
__device__ __forceinline__ void cross3_(float ax,float ay,float az,
                                        float bx,float by,float bz,
                                        float &cx,float &cy,float &cz){
    cx = fsub_(fmul_(ay,bz), fmul_(az,by));
    cy = fsub_(fmul_(az,bx), fmul_(ax,bz));
    cz = fsub_(fmul_(ax,by), fmul_(ay,bx));
}
__device__ __forceinline__ float d2_exact(float xi,float yi,float zi,
                                          float xj,float yj,float zj){
    float dx = fsub_(xj,xi), dy = fsub_(yj,yi), dz = fsub_(zj,zi);
    return fadd_(fadd_(fmul_(dx,dx), fmul_(dy,dy)), fmul_(dz,dz));
}

// ---- FP32 Cody-Waite 2pi reduction ----
#define INV_2PI  0.15915494309189535f
#define PI2_C1   6.2831855f
#define PI2_C2  -1.7484555e-07f
#define PI2_C3  -5.4469782e-15f
__device__ __forceinline__ float red2pi_(float ang){
    float k = rintf(ang * INV_2PI);
    float r = fmaf(-k, PI2_C1, ang);
    r = fmaf(-k, PI2_C2, r);
    r = fmaf(-k, PI2_C3, r);
    return r;
}

// ---- per-node orientation matrix + AD ----
__device__ void node_work(const float* __restrict__ X, float* __restrict__ outAD,
                          int id, float* __restrict__ sOmRow){
    int b = id / NN, n = id % NN;

    float O0=0,O1=0,O2=0,O3v=0,O4=0,O5=0,O6=0,O7=0,O8=0;
    float a0=0,a1=0,a2=0;

    if (n >= 1 && n <= NN-3){
        const float* Xb = X + b*NN*3;
        float p0x=Xb[(n-1)*3+0], p0y=Xb[(n-1)*3+1], p0z=Xb[(n-1)*3+2];
        float p1x=Xb[(n  )*3+0], p1y=Xb[(n  )*3+1], p1z=Xb[(n  )*3+2];
        float p2x=Xb[(n+1)*3+0], p2y=Xb[(n+1)*3+1], p2z=Xb[(n+1)*3+2];
        float p3x=Xb[(n+2)*3+0], p3y=Xb[(n+2)*3+1], p3z=Xb[(n+2)*3+2];

        float u2x=fsub_(p1x,p0x), u2y=fsub_(p1y,p0y), u2z=fsub_(p1z,p0z); norm3_(u2x,u2y,u2z);
        float u1x=fsub_(p2x,p1x), u1y=fsub_(p2y,p1y), u1z=fsub_(p2z,p1z); norm3_(u1x,u1y,u1z);
        float u0x=fsub_(p3x,p2x), u0y=fsub_(p3y,p2y), u0z=fsub_(p3z,p2z); norm3_(u0x,u0y,u0z);

        float n2x,n2y,n2z; cross3_(u2x,u2y,u2z,u1x,u1y,u1z,n2x,n2y,n2z); norm3_(n2x,n2y,n2z);
        float n1x,n1y,n1z; cross3_(u1x,u1y,u1z,u0x,u0y,u0z,n1x,n1y,n1z); norm3_(n1x,n1y,n1z);

        const float lo = (float)(-1.0 + 1e-6);
        const float hi = (float)( 1.0 - 1e-6);
        float cosA = fminf(fmaxf(-dot3_(u1x,u1y,u1z,u0x,u0y,u0z), lo), hi);
        float A = acosf(cosA);
        float cosD = fminf(fmaxf(dot3_(n2x,n2y,n2z,n1x,n1y,n1z), lo), hi);
        float s = dot3_(u2x,u2y,u2z,n1x,n1y,n1z);
        float sg = (s > 0.0f) ? 1.0f : ((s < 0.0f) ? -1.0f : 0.0f);
        float Dang = fmul_(sg, acosf(cosD));

        float sA = sinf(A);
        a0 = cosf(A);
        a1 = fmul_(sA, cosf(Dang));
        a2 = fmul_(sA, sinf(Dang));

        float o1x=fsub_(u2x,u1x), o1y=fsub_(u2y,u1y), o1z=fsub_(u2z,u1z); norm3_(o1x,o1y,o1z);
        float cx,cy,cz; cross3_(o1x,o1y,o1z,n2x,n2y,n2z,cx,cy,cz);
        O0=o1x; O1=o1y; O2=o1z; O3v=n2x; O4=n2y; O5=n2z; O6=cx; O7=cy; O8=cz;
    }
    sOmRow[0]=O0; sOmRow[1]=O1; sOmRow[2]=O2; sOmRow[3]=O3v; sOmRow[4]=O4;
    sOmRow[5]=O5; sOmRow[6]=O6; sOmRow[7]=O7; sOmRow[8]=O8;
    outAD[id*3+0]=a0; outAD[id*3+1]=a1; outAD[id*3+2]=a2;
}

// ---- pre-pass: pack coords + squared norms ----
__global__ void pack_kernel(const float* __restrict__ X){
    int id = blockIdx.x*blockDim.x + threadIdx.x;
    if (id < BB*NN){
        float x = X[id*3+0], y = X[id*3+1], z = X[id*3+2];
        g_pts4[id] = make_float4(x, y, z, fmaf(z,z, fmaf(y,y, x*x)));
    }
}

// ============================================================================
// Fused kernel v16: value-exact sampled threshold + single verified scan.
// thr = exact 10th-smallest of 512 sampled fast-d2' (expected full rank ~80).
// keep = {d2' < 1.06*thr}; certificate strict = #{d2' < thr} >= 30 ensures
// kept superset of exact top-30 (0.06*thr >> fp error). Convergent fallback.
// ============================================================================
#define TPB 256
#define RB  8
#define CAP 448
#define SMP 512

__global__ __launch_bounds__(TPB) void fused_kernel(
    const float* __restrict__ X, float* __restrict__ out)
{
    __shared__ u64   cand[RB][CAP];    // 28KB
    __shared__ float stD[RB][KK];
    __shared__ int   stI[RB][KK];
    __shared__ float sOm[RB][9];
    __shared__ float sThr[RB];
    __shared__ float sfreq[8];
    __shared__ float smu[15];
    __shared__ int   scnt[RB];
    __shared__ int   sstr[RB];

    float* outP  = out + OFF_POS;
    float* outAD = out + OFF_AD;
    float* outO  = out + OFF_OF;
    float* outG  = out + OFF_GS;
    float* outD  = out + OFF_DN;
    float* outE  = out + OFF_EI;

    const int t = threadIdx.x, w = t >> 5, lane = t & 31;
    const int blk = blockIdx.x;
    const int b   = blk / (NN/RB);
    const int r0  = (blk % (NN/RB))*RB;
    const int bNN = b*NN;
    const float* Xb = X + b*NN*3;
    const u32 FULL = 0xffffffffu;

    if (t < RB){
        node_work(X, outAD, bNN + r0 + t, sOm[t]);
        scnt[t] = 0;
        sstr[t] = 0;
    }
    if (t >= 32 && t < 64){
        int u = t - 32;
        if (u < 8){
            float argf = __fmul_rn((float)(2*u), -0.5756462732485115f);
            sfreq[u] = (float)exp((double)argf);
        }
        if (u < 15) smu[u] = (float)((double)u * (20.0/14.0));
    }

    // packed row registers: pair (q, q+4); nr biased by +1.01
    u64 xr2[4], yr2[4], zr2[4], nr2[4];
    #pragma unroll
    for (int q = 0; q < 4; q++){
        float4 pa = g_pts4[bNN + r0 + q];
        float4 pb = g_pts4[bNN + r0 + q + 4];
        xr2[q] = pack2(pa.x, pb.x);
        yr2[q] = pack2(pa.y, pb.y);
        zr2[q] = pack2(pa.z, pb.z);
        nr2[q] = pack2(pa.w + 1.01f, pb.w + 1.01f);
    }
    const u64 M2 = pack2(-2.0f, -2.0f);

    // own-row scalars for sample/fallback (warp w = row w)
    float4 prow = g_pts4[bNN + r0 + w];
    const float xi_s = prow.x, yi_s = prow.y, zi_s = prow.z;
    const float nrb_s = prow.w + 1.01f;

    // ---- sample phase: exact 10th-smallest of 512 sampled fast-d2' ----
    {
        float v[SMP/32];
        #pragma unroll
        for (int q = 0; q < SMP/32; q++){
            int j = q*32 + lane;
            float4 p = g_pts4[bNN + j];
            float s  = fmaf(zi_s, p.z, fmaf(yi_s, p.y, xi_s*p.x));
            v[q] = fmaf(-2.0f, s, nrb_s + p.w);
        }
        float t10 = 0.0f;
        #pragma unroll
        for (int k = 0; k < 10; k++){
            float lm = v[0]; int ls = 0;
            #pragma unroll
            for (int q = 1; q < SMP/32; q++)
                if (v[q] < lm){ lm = v[q]; ls = q; }
            float wm = lm;
            #pragma unroll
            for (int off = 16; off; off >>= 1)
                wm = fminf(wm, __shfl_xor_sync(FULL, wm, off));
            if (k == 9) t10 = wm;
            else if (lm == wm){
                #pragma unroll
                for (int q = 0; q < SMP/32; q++) if (q == ls) v[q] = 1e30f;
            }
        }
        if (lane == 0) sThr[w] = t10;
    }
    __syncthreads();

    // packed thresholds: keep = 1.06*thr, strict = thr (negated)
    u64 nThrK2[4], nThrB2[4];
    #pragma unroll
    for (int q = 0; q < 4; q++){
        nThrK2[q] = pack2(-1.06f*sThr[q], -1.06f*sThr[q+4]);
        nThrB2[q] = pack2(-sThr[q],       -sThr[q+4]);
    }

    // ---- single packed scan: keep-append + strict count ----
    #pragma unroll 2
    for (int m = 0; m < NN/TPB; m++){
        int j = m*TPB + t;
        float4 p = g_pts4[bNN + j];
        u64 xjj = pack2(p.x, p.x);
        u64 yjj = pack2(p.y, p.y);
        u64 zjj = pack2(p.z, p.z);
        u64 njj = pack2(p.w, p.w);
        #pragma unroll
        for (int q = 0; q < 4; q++){
            u64 s2 = fma2(xr2[q], xjj, fma2(yr2[q], yjj, mul2(zr2[q], zjj)));
            u64 d2 = fma2(M2, s2, add2(nr2[q], njj));
            u64 df = add2(d2, nThrK2[q]);
            if (df & 0x8000000080000000ull){
                u64 dfb = add2(d2, nThrB2[q]);
                if ((u32)(df >> 31) & 1u){
                    int pos = atomicAdd(&scnt[q], 1);
                    if (pos < CAP) cand[q][pos] = (u64)j;
                    if ((u32)(dfb >> 31) & 1u) atomicAdd(&sstr[q], 1);
                }
                if (df >> 63){
                    int pos = atomicAdd(&scnt[q+4], 1);
                    if (pos < CAP) cand[q+4][pos] = (u64)j;
                    if (dfb >> 63) atomicAdd(&sstr[q+4], 1);
                }
            }
        }
    }
    __syncthreads();

    // ---- certificate check + convergent fallback (warp w = row w) ----
    int c;
    {
        int cnt = scnt[w], str = sstr[w];
        int att = 0;
        float thr = sThr[w];
        while ((str < KK || cnt > CAP) && att < 16){
            thr = (str < KK) ? thr*2.0f : thr*0.75f;
            float tk = 1.06f*thr;
            cnt = 0; str = 0;
            for (int m = 0; m < NN/32; m++){
                int j = m*32 + lane;
                float4 p = g_pts4[bNN + j];
                float s  = fmaf(zi_s, p.z, fmaf(yi_s, p.y, xi_s*p.x));
                float d2 = fmaf(-2.0f, s, nrb_s + p.w);
                bool kp = d2 < tk;
                u32 mk = __ballot_sync(FULL, kp);
                str += __popc(__ballot_sync(FULL, d2 < thr));
                if (kp){
                    int pos = cnt + __popc(mk & ((1u << lane) - 1u));
                    if (pos < CAP) cand[w][pos] = (u64)j;
                }
                cnt += __popc(mk);
            }
            att++;
        }
        c = min(cnt, CAP);
    }

    // ---- extraction: exact (D, j) keys + in-place rank (warp w = row w) ----
    {
        const int row = r0 + w;
        const int base = (bNN + row)*KK;
        const float xi = Xb[row*3+0], yi = Xb[row*3+1], zi = Xb[row*3+2];

        for (int idx = lane; idx < c; idx += 32){
            u32 j = (u32)cand[w][idx];
            float4 pj = g_pts4[bNN + j];
            float d2 = d2_exact(xi,yi,zi, pj.x,pj.y,pj.z);
            float D  = __fsqrt_rn(fadd_(d2, 1e-6f));
            cand[w][idx] = ((u64)__float_as_uint(D) << 32) | j;
        }
        __syncwarp();

        for (int idx = lane; idx < c; idx += 32){
            u64 k = cand[w][idx];
            int rank = 0;
            for (int cc = 0; cc < c; cc++)
                rank += (cand[w][cc] < k) ? 1 : 0;
            if (rank < KK){
                u32 jj = (u32)(k & 0xFFFFFFFFull);
                float D = __uint_as_float((u32)(k >> 32));
                outD[base + rank] = D;
                outE[base + rank] = (float)jj;
                stD[w][rank] = D;
                stI[w][rank] = (int)jj;
            }
        }
    }
    __syncthreads();

    // ---- edge phase A: positional encodings (8 x 30 x 16, coalesced) ----
    for (int id = t; id < RB*KK*16; id += TPB){
        int r = id / (KK*16);
        int q = id - r*(KK*16);
        int k = q >> 4, m = q & 15;
        int i = r0 + r;
        int j = stI[r][k];
        float d = fsub_((float)j, (float)i);
        float ang = fmul_(d, sfreq[m & 7]);
        float rr = red2pi_(ang);
        outP[(size_t)(bNN + i)*(KK*16) + q] = (m < 8) ? __cosf(rr) : __sinf(rr);
    }

    // ---- edge phase B: gaussian smearing (8 x 30 x 15, coalesced) ----
    for (int id = t; id < RB*KK*15; id += TPB){
        int r = id / (KK*15);
        int q = id - r*(KK*15);
        int k = q / 15, m = q - k*15;
        float D  = stD[r][k];
        float tt = fsub_(D, smu[m]) * 0.74999998f;
        outG[(size_t)(bNN + r0 + r)*(KK*15) + q] = __expf(-tt*tt);
    }

    // ---- edge phase C: dU via rsqrt normalize (8 x 30 edges) ----
    if (t < RB*KK){
        int r = t / KK, k = t - r*KK;
        int i = r0 + r;
        int j = stI[r][k];
        float dx = fsub_(Xb[j*3+0], Xb[i*3+0]);
        float dy = fsub_(Xb[j*3+1], Xb[i*3+1]);
        float dz = fsub_(Xb[j*3+2], Xb[i*3+2]);
        const float* Om = sOm[r];
        float v0 = dot3_(Om[0],Om[1],Om[2], dx,dy,dz);
        float v1 = dot3_(Om[3],Om[4],Om[5], dx,dy,dz);
        float v2 = dot3_(Om[6],Om[7],Om[8], dx,dy,dz);
        float s  = dot3_(v0,v1,v2,v0,v1,v2);
        float rn = rsqrtf(fmaxf(s, 1e-24f));
        size_t o = (size_t)((bNN + i)*KK + k)*3;
        outO[o+0] = v0*rn;
        outO[o+1] = v1*rn;
        outO[o+2] = v2*rn;
    }
}

// ============================================================================
extern "C" void kernel_launch(void* const* d_in, const int* in_sizes, int n_in,
                              void* d_out, int out_size)
{
    const float* X = (const float*)d_in[0];
    float* out = (float*)d_out;
    pack_kernel<<<(BB*NN + 255)/256, 256>>>(X);
    fused_kernel<<<BB*NN/RB, TPB>>>(X, out);
}